// round 14
// baseline (speedup 1.0000x reference)
#include <cuda_runtime.h>
#include <cuda_fp8.h>
#include <stdint.h>

#define NR 8192
#define DD 512
#define BM 128
#define BKB 64               // k bytes (fp8 elems) per stage
#define NKT (DD / BKB)       // 8 k-tiles
#define NBLK (NR / BM)       // 64
#define NTRI (NBLK * (NBLK + 1) / 2)   // 2080 tiles
#define STAGES 4
#define SSTB 80                        // smem row stride bytes (conflict-free ldmatrix)
#define TILE_SMEM (BM * SSTB)          // 10240
#define STAGE_SMEM (2 * TILE_SMEM)     // 20480
#define SMEM_TOTAL (STAGES * STAGE_SMEM)  // 81920
#define RBLK 256                       // reduce blocks

// ---- device scratch ----
__device__ __align__(16) uint8_t g_ne[NR * DD];   // e4m3 normalized embeddings
__device__ float g_pos[NR];
__device__ float g_Spart[NBLK][NR];
__device__ float g_blocksum[RBLK];
__device__ int g_cnt;   // zero-init; self-resets each run

// ============================================================
// Kernel A: normalize -> e4m3 via paired cvt.e4m3x2 (2 rows/block)
// ============================================================
__global__ void __launch_bounds__(256) norm_kernel(const float* __restrict__ emb,
                                                   const float* __restrict__ tgt) {
    const int tid = threadIdx.x;
    const int h = tid >> 7;        // which row of the pair
    const int t = tid & 127;
    const int wh = (tid >> 5) & 3; // warp within half
    const int l = tid & 31;
    const int row = blockIdx.x * 2 + h;

    float4 a = reinterpret_cast<const float4*>(emb + (size_t)row * DD)[t];
    float4 b = reinterpret_cast<const float4*>(tgt + (size_t)row * DD)[t];

    float ee = a.x*a.x + a.y*a.y + a.z*a.z + a.w*a.w;
    float tt = b.x*b.x + b.y*b.y + b.z*b.z + b.w*b.w;
    float et = a.x*b.x + a.y*b.y + a.z*b.z + a.w*b.w;
#pragma unroll
    for (int o = 16; o > 0; o >>= 1) {
        ee += __shfl_xor_sync(0xFFFFFFFFu, ee, o);
        tt += __shfl_xor_sync(0xFFFFFFFFu, tt, o);
        et += __shfl_xor_sync(0xFFFFFFFFu, et, o);
    }
    __shared__ float sred[2][3][4];
    if (l == 0) { sred[h][0][wh] = ee; sred[h][1][wh] = tt; sred[h][2][wh] = et; }
    __syncthreads();
    ee = sred[h][0][0] + sred[h][0][1] + sred[h][0][2] + sred[h][0][3];
    tt = sred[h][1][0] + sred[h][1][1] + sred[h][1][2] + sred[h][1][3];
    et = sred[h][2][0] + sred[h][2][1] + sred[h][2][2] + sred[h][2][3];

    float inv_e = rsqrtf(ee);
    if (t == 0) g_pos[row] = et * inv_e * rsqrtf(tt);

    // paired converts: d = {cvt(srcA)<<8 | cvt(srcB)} -> pass (y,x) so x lands in byte0
    uint16_t lo, hi;
    asm("cvt.rn.satfinite.e4m3x2.f32 %0, %1, %2;"
        : "=h"(lo) : "f"(a.y * inv_e), "f"(a.x * inv_e));
    asm("cvt.rn.satfinite.e4m3x2.f32 %0, %1, %2;"
        : "=h"(hi) : "f"(a.w * inv_e), "f"(a.z * inv_e));
    uint32_t p = (uint32_t)lo | ((uint32_t)hi << 16);
    reinterpret_cast<uint32_t*>(g_ne)[(size_t)row * (DD / 4) + t] = p;
}

// ============================================================
// MMA / cp.async helpers
// ============================================================
__device__ __forceinline__ void ldsm_x4(uint32_t& r0, uint32_t& r1, uint32_t& r2, uint32_t& r3,
                                        uint32_t addr) {
    asm volatile("ldmatrix.sync.aligned.m8n8.x4.shared.b16 {%0,%1,%2,%3}, [%4];"
                 : "=r"(r0), "=r"(r1), "=r"(r2), "=r"(r3) : "r"(addr));
}
__device__ __forceinline__ void mma_fp8(float c[4], const uint32_t a[4], uint32_t b0, uint32_t b1) {
    asm volatile(
        "mma.sync.aligned.m16n8k32.row.col.f32.e4m3.e4m3.f32 "
        "{%0,%1,%2,%3}, {%4,%5,%6,%7}, {%8,%9}, {%0,%1,%2,%3};"
        : "+f"(c[0]), "+f"(c[1]), "+f"(c[2]), "+f"(c[3])
        : "r"(a[0]), "r"(a[1]), "r"(a[2]), "r"(a[3]), "r"(b0), "r"(b1));
}
__device__ __forceinline__ void cp16(uint32_t dst, const void* src) {
    asm volatile("cp.async.cg.shared.global [%0], [%1], 16;" :: "r"(dst), "l"(src));
}
__device__ __forceinline__ void cp_commit() {
    asm volatile("cp.async.commit_group;" ::: "memory");
}
template <int N>
__device__ __forceinline__ void cp_wait() {
    asm volatile("cp.async.wait_group %0;" :: "n"(N) : "memory");
}

// ============================================================
// Kernel B: upper-triangle fp8 GEMM + exp(2x) row/col sums  [R11/R13, unchanged]
// ============================================================
__global__ void __launch_bounds__(256, 2) gemm_lse_kernel() {
    extern __shared__ char smem[];
    const uint32_t sb = (uint32_t)__cvta_generic_to_shared(smem);

    const int tid = threadIdx.x;
    const int lane = tid & 31;
    const int wid = tid >> 5;
    const int warp_m = wid >> 1;
    const int warp_n = wid & 1;
    const int ksel = wid & 1;

    int t = blockIdx.x;
    int bi = (int)(64.5f - sqrtf(64.5f * 64.5f - 2.0f * (float)t));
    if (bi < 0) bi = 0;
    if (bi > 63) bi = 63;
#define TRI_S(b) ((b) * 64 - ((b) * ((b) - 1)) / 2)
    while (bi > 0 && TRI_S(bi) > t) bi--;
    while (bi < 63 && TRI_S(bi + 1) <= t) bi++;
    const int bj = bi + (t - TRI_S(bi));
    const bool diag = (bi == bj);

    const uint8_t* gA = g_ne + (size_t)bi * BM * DD;
    const uint8_t* gB = g_ne + (size_t)bj * BM * DD;

    const int r0c = tid >> 2;
    const int r1c = (tid + 256) >> 2;
    const int kc0 = (tid & 3) * 16;

    const int lrow = lane & 15;
    const int lkb  = (lane >> 4) * 16;
    const uint32_t aoff0 = (uint32_t)((warp_m * 32 + lrow) * SSTB + lkb);
    const uint32_t aoff1 = aoff0 + 16 * SSTB;
    uint32_t boff[4];
#pragma unroll
    for (int nj = 0; nj < 4; nj++)
        boff[nj] = (uint32_t)((warp_n * 64 + nj * 16 + lrow) * SSTB + lkb) + TILE_SMEM;

    float acc[2][8][4];
#pragma unroll
    for (int mi = 0; mi < 2; mi++)
#pragma unroll
        for (int ni = 0; ni < 8; ni++)
#pragma unroll
            for (int k = 0; k < 4; k++) acc[mi][ni][k] = 0.f;

#pragma unroll
    for (int p = 0; p < STAGES - 1; p++) {
        uint32_t base = sb + p * STAGE_SMEM;
        cp16(base + r0c * SSTB + kc0, gA + (size_t)r0c * DD + p * BKB + kc0);
        cp16(base + r1c * SSTB + kc0, gA + (size_t)r1c * DD + p * BKB + kc0);
        cp16(base + TILE_SMEM + r0c * SSTB + kc0, gB + (size_t)r0c * DD + p * BKB + kc0);
        cp16(base + TILE_SMEM + r1c * SSTB + kc0, gB + (size_t)r1c * DD + p * BKB + kc0);
        cp_commit();
    }

#pragma unroll
    for (int kt = 0; kt < NKT; kt++) {
        cp_wait<STAGES - 2>();
        __syncthreads();

        uint32_t base = sb + (kt & (STAGES - 1)) * STAGE_SMEM;
        const uint32_t o0 = (uint32_t)ksel * 32;
        const uint32_t o1 = o0 ^ 32;

        uint32_t a[2][4], b[4][4];
        ldsm_x4(a[0][0], a[0][1], a[0][2], a[0][3], base + aoff0 + o0);
        ldsm_x4(a[1][0], a[1][1], a[1][2], a[1][3], base + aoff1 + o0);
#pragma unroll
        for (int nj = 0; nj < 4; nj++)
            ldsm_x4(b[nj][0], b[nj][1], b[nj][2], b[nj][3], base + boff[nj] + o0);

        if (kt + STAGES - 1 < NKT) {
            const int kl = kt + STAGES - 1;
            uint32_t lb = sb + (kl & (STAGES - 1)) * STAGE_SMEM;
            cp16(lb + r0c * SSTB + kc0, gA + (size_t)r0c * DD + kl * BKB + kc0);
            cp16(lb + r1c * SSTB + kc0, gA + (size_t)r1c * DD + kl * BKB + kc0);
            cp16(lb + TILE_SMEM + r0c * SSTB + kc0, gB + (size_t)r0c * DD + kl * BKB + kc0);
            cp16(lb + TILE_SMEM + r1c * SSTB + kc0, gB + (size_t)r1c * DD + kl * BKB + kc0);
        }
        cp_commit();

#pragma unroll
        for (int mi = 0; mi < 2; mi++)
#pragma unroll
            for (int ni = 0; ni < 8; ni++)
                mma_fp8(acc[mi][ni], a[mi], b[ni >> 1][ni & 1], b[ni >> 1][(ni & 1) + 2]);

        ldsm_x4(a[0][0], a[0][1], a[0][2], a[0][3], base + aoff0 + o1);
        ldsm_x4(a[1][0], a[1][1], a[1][2], a[1][3], base + aoff1 + o1);
#pragma unroll
        for (int nj = 0; nj < 4; nj++)
            ldsm_x4(b[nj][0], b[nj][1], b[nj][2], b[nj][3], base + boff[nj] + o1);
#pragma unroll
        for (int mi = 0; mi < 2; mi++)
#pragma unroll
            for (int ni = 0; ni < 8; ni++)
                mma_fp8(acc[mi][ni], a[mi], b[ni >> 1][ni & 1], b[ni >> 1][(ni & 1) + 2]);
    }

    // ---- epilogue ----
#pragma unroll
    for (int mi = 0; mi < 2; mi++)
#pragma unroll
        for (int ni = 0; ni < 8; ni++)
#pragma unroll
            for (int k = 0; k < 4; k++) {
                float x = acc[mi][ni][k];
                acc[mi][ni][k] = __expf(x + x);
            }

    float* rowbuf = (float*)smem;               // [2][128]
    float* colbuf = (float*)(smem + 1024);      // [4][128]
    __syncthreads();

#pragma unroll
    for (int mi = 0; mi < 2; mi++) {
        float r0 = 0.f, r1 = 0.f;
#pragma unroll
        for (int ni = 0; ni < 8; ni++) {
            r0 += acc[mi][ni][0] + acc[mi][ni][1];
            r1 += acc[mi][ni][2] + acc[mi][ni][3];
        }
        r0 += __shfl_xor_sync(0xFFFFFFFFu, r0, 1);
        r0 += __shfl_xor_sync(0xFFFFFFFFu, r0, 2);
        r1 += __shfl_xor_sync(0xFFFFFFFFu, r1, 1);
        r1 += __shfl_xor_sync(0xFFFFFFFFu, r1, 2);
        if ((lane & 3) == 0) {
            int rr = warp_m * 32 + mi * 16 + (lane >> 2);
            rowbuf[warp_n * 128 + rr] = r0;
            rowbuf[warp_n * 128 + rr + 8] = r1;
        }
    }

    if (!diag) {
#pragma unroll
        for (int ni = 0; ni < 8; ni++) {
            float ce = acc[0][ni][0] + acc[0][ni][2] + acc[1][ni][0] + acc[1][ni][2];
            float co = acc[0][ni][1] + acc[0][ni][3] + acc[1][ni][1] + acc[1][ni][3];
            ce += __shfl_xor_sync(0xFFFFFFFFu, ce, 4);
            ce += __shfl_xor_sync(0xFFFFFFFFu, ce, 8);
            ce += __shfl_xor_sync(0xFFFFFFFFu, ce, 16);
            co += __shfl_xor_sync(0xFFFFFFFFu, co, 4);
            co += __shfl_xor_sync(0xFFFFFFFFu, co, 8);
            co += __shfl_xor_sync(0xFFFFFFFFu, co, 16);
            if (lane < 4) {
                int cc = warp_n * 64 + ni * 8 + lane * 2;
                colbuf[warp_m * 128 + cc] = ce;
                colbuf[warp_m * 128 + cc + 1] = co;
            }
        }
    }
    __syncthreads();

    if (tid < 128) {
        g_Spart[bj][bi * BM + tid] = rowbuf[tid] + rowbuf[128 + tid];
        if (!diag)
            g_Spart[bi][bj * BM + tid] =
                colbuf[tid] + colbuf[128 + tid] + colbuf[256 + tid] + colbuf[384 + tid];
    }
}

// ============================================================
// Kernel C: coalesced per-row combine + final  [R13, unchanged]
// ============================================================
__global__ void reduce_kernel(float* __restrict__ out) {
    const int tid = threadIdx.x;
    const int wid = tid >> 5;
    const int lane = tid & 31;
    const int row = blockIdx.x * 32 + lane;

    float s = 0.f;
#pragma unroll
    for (int k = 0; k < 8; k++) s += g_Spart[wid * 8 + k][row];   // coalesced per warp

    __shared__ float sp[8][32];
    __shared__ int slast;
    sp[wid][lane] = s;
    __syncthreads();

    if (wid == 0) {
        float tot = sp[0][lane] + sp[1][lane] + sp[2][lane] + sp[3][lane]
                  + sp[4][lane] + sp[5][lane] + sp[6][lane] + sp[7][lane];
        float v = logf(tot) - 2.f * g_pos[row];
#pragma unroll
        for (int o = 16; o > 0; o >>= 1) v += __shfl_xor_sync(0xFFFFFFFFu, v, o);
        if (lane == 0) {
            g_blocksum[blockIdx.x] = v;
            __threadfence();
            int prev = atomicAdd(&g_cnt, 1);
            slast = (prev == RBLK - 1) ? 1 : 0;
        }
    }
    __syncthreads();
    if (slast && tid < 32) {
        __threadfence();
        float x = 0.f;
#pragma unroll
        for (int k = 0; k < RBLK / 32; k++) x += g_blocksum[tid * (RBLK / 32) + k];
#pragma unroll
        for (int o = 16; o > 0; o >>= 1) x += __shfl_xor_sync(0xFFFFFFFFu, x, o);
        if (tid == 0) {
            out[0] = x * (1.0f / (2.0f * NR));
            g_cnt = 0;   // reset for next graph replay
        }
    }
}

// ============================================================
extern "C" void kernel_launch(void* const* d_in, const int* in_sizes, int n_in,
                              void* d_out, int out_size) {
    const float* emb = (const float*)d_in[0];
    const float* tgt = (const float*)d_in[1];
    float* out = (float*)d_out;

    cudaFuncSetAttribute(gemm_lse_kernel, cudaFuncAttributeMaxDynamicSharedMemorySize, SMEM_TOTAL);

    norm_kernel<<<NR / 2, 256>>>(emb, tgt);
    gemm_lse_kernel<<<NTRI, 256, SMEM_TOTAL>>>();
    reduce_kernel<<<RBLK, 256>>>(out);
}